// round 6
// baseline (speedup 1.0000x reference)
#include <cuda_runtime.h>
#include <cuda_fp16.h>
#include <cstdint>

#define B_  2
#define C_  256
#define H_  128
#define W_  128
#define HW_ (H_ * W_)
#define NH  32
#define NW  32

// ---------------------------------------------------------------------------
// Static scratch (no runtime allocation allowed).
// ---------------------------------------------------------------------------
__device__ __align__(256) __half g_Wh[3][C_ * C_];           // fp16(W), [O][K]
__device__ __align__(256) __half g_Xh[4][(size_t)HW_ * C_];  // fp16(X^T), [hw][c]
__device__ __align__(256) __half g_QKV[3][(size_t)B_ * C_ * HW_]; // Q,K,V fp16 [b][c][hw]

// ---------------------------------------------------------------------------
// Helpers
// ---------------------------------------------------------------------------
__device__ __forceinline__ uint32_t smem_u32(const void* p) {
  uint32_t a;
  asm("{ .reg .u64 t; cvta.to.shared.u64 t, %1; cvt.u32.u64 %0, t; }" : "=r"(a) : "l"(p));
  return a;
}

#define CP_ASYNC16(s, g) \
  asm volatile("cp.async.cg.shared.global [%0], [%1], 16;" :: "r"(s), "l"(g))
#define CP_COMMIT() asm volatile("cp.async.commit_group;" ::: "memory")
#define CP_WAIT0()  asm volatile("cp.async.wait_group 0;" ::: "memory")
#define CP_WAIT1()  asm volatile("cp.async.wait_group 1;" ::: "memory")

__device__ __forceinline__ void ldsm_x4(uint32_t* r, uint32_t addr) {
  asm volatile("ldmatrix.sync.aligned.m8n8.x4.shared.b16 {%0,%1,%2,%3}, [%4];"
               : "=r"(r[0]), "=r"(r[1]), "=r"(r[2]), "=r"(r[3]) : "r"(addr));
}

__device__ __forceinline__ void mma_f16(float* c, const uint32_t* a, const uint32_t* b) {
  asm volatile(
      "mma.sync.aligned.m16n8k16.row.col.f32.f16.f16.f32 "
      "{%0,%1,%2,%3}, {%4,%5,%6,%7}, {%8,%9}, {%0,%1,%2,%3};"
      : "+f"(c[0]), "+f"(c[1]), "+f"(c[2]), "+f"(c[3])
      : "r"(a[0]), "r"(a[1]), "r"(a[2]), "r"(a[3]), "r"(b[0]), "r"(b[1]));
}

// smem tile: 128 rows x 32 fp16 (64B rows, 4 x 16B chunks, XOR swizzle)
__device__ __forceinline__ uint32_t soff(int r, int c) {
  return (uint32_t)(r * 64 + ((c ^ ((r >> 1) & 3)) << 4));
}

// load 4 consecutive halves as float4
__device__ __forceinline__ float4 ld_h4(const __half* p) {
  uint2 u = *(const uint2*)p;
  __half2 h0 = *(__half2*)&u.x;
  __half2 h1 = *(__half2*)&u.y;
  float2 f0 = __half22float2(h0);
  float2 f1 = __half22float2(h1);
  return make_float4(f0.x, f0.y, f1.x, f1.y);
}

// ---------------------------------------------------------------------------
// Kernel 0a: weights -> fp16.
// ---------------------------------------------------------------------------
__global__ void __launch_bounds__(256) convert_w_kernel(
    const float* __restrict__ qw, const float* __restrict__ kw,
    const float* __restrict__ vw) {
  int idx = blockIdx.x * 256 + threadIdx.x;
  int p = idx >> 16;
  int r = idx & 0xFFFF;
  const float* w = (p == 0) ? qw : (p == 1) ? kw : vw;
  g_Wh[p][r] = __float2half_rn(w[r]);
}

// ---------------------------------------------------------------------------
// Kernel 0b: transpose X [c][hw] -> [hw][c] into fp16.
// ---------------------------------------------------------------------------
__global__ void __launch_bounds__(256) convert_x_kernel(
    const float* __restrict__ blue, const float* __restrict__ white) {
  __shared__ float t[32][33];
  const int hw0 = blockIdx.x * 32;
  const int c0 = blockIdx.y * 32;
  const int slab = blockIdx.z;
  const float* src = (slab < 2) ? blue + (size_t)slab * C_ * HW_
                                : white + (size_t)(slab - 2) * C_ * HW_;
  const int tx = threadIdx.x, ty = threadIdx.y;
#pragma unroll
  for (int it = 0; it < 4; it++) {
    int c = it * 8 + ty;
    t[c][tx] = src[(size_t)(c0 + c) * HW_ + hw0 + tx];
  }
  __syncthreads();
  const int tid = ty * 32 + tx;
  const int cp = tid & 15;
  const int hy = tid >> 4;
  __half* Xh = g_Xh[slab];
#pragma unroll
  for (int it = 0; it < 2; it++) {
    int hw = it * 16 + hy;
    __half2 vh;
    vh.x = __float2half_rn(t[cp * 2][hw]);
    vh.y = __float2half_rn(t[cp * 2 + 1][hw]);
    *(__half2*)(Xh + (size_t)(hw0 + hw) * C_ + c0 + cp * 2) = vh;
  }
}

// ---------------------------------------------------------------------------
// Kernel 1: single-pass fp16 GEMM via mma.sync (HMMA).
// Out[p][b][m][n] = sum_k W[m][k] * X^T[n][k] + bias[m]   (fp16 out)
// CTA: 128(m) x 128(n), BK=32, 8 warps (2x4), warp 64x32, cp.async pipeline.
// ---------------------------------------------------------------------------
__global__ void __launch_bounds__(256, 2) gemm_mma_kernel(
    const float* __restrict__ qb, const float* __restrict__ kb,
    const float* __restrict__ vb) {
  extern __shared__ char sm[];
  const uint32_t sbase = smem_u32(sm);

  const int tid = threadIdx.x;
  const int lane = tid & 31;
  const int wid = tid >> 5;
  const int wm = wid >> 2;          // 0..1
  const int wn = wid & 3;           // 0..3

  const int z = blockIdx.z;         // 0..5
  const int p = z >> 1;
  const int b = z & 1;
  const int m0 = blockIdx.y * 128;
  const int n0 = blockIdx.x * 128;
  const int slab = (p == 0) ? b : 2 + b;

  const __half* __restrict__ gA = g_Wh[p] + m0 * C_;
  const __half* __restrict__ gB = g_Xh[slab] + (size_t)n0 * C_;

  const int stg_r = tid >> 2;           // rows this thread stages (and +64)
  const int stg_c = tid & 3;

  float acc[4][4][4];
#pragma unroll
  for (int mt = 0; mt < 4; mt++)
#pragma unroll
    for (int nt = 0; nt < 4; nt++)
#pragma unroll
      for (int e = 0; e < 4; e++) acc[mt][nt][e] = 0.f;

#define ISSUE_STAGE(ks, buf)                                                     \
  {                                                                              \
    const int k0 = (ks) * 32;                                                    \
    _Pragma("unroll")                                                            \
    for (int it = 0; it < 2; it++) {                                             \
      int r = stg_r + it * 64;                                                   \
      uint32_t so = sbase + (buf) * 16384 + soff(r, stg_c);                      \
      CP_ASYNC16(so,        gA + r * C_ + k0 + stg_c * 8);                       \
      CP_ASYNC16(so + 8192, gB + (size_t)r * C_ + k0 + stg_c * 8);               \
    }                                                                            \
    CP_COMMIT();                                                                 \
  }

  ISSUE_STAGE(0, 0);

  for (int ks = 0; ks < 8; ks++) {
    const int buf = ks & 1;
    if (ks + 1 < 8) {
      ISSUE_STAGE(ks + 1, buf ^ 1);
      CP_WAIT1();
    } else {
      CP_WAIT0();
    }
    __syncthreads();

    const uint32_t Ab = sbase + buf * 16384;
    const uint32_t Bb = Ab + 8192;

#pragma unroll
    for (int kc = 0; kc < 2; kc++) {
      uint32_t ah[4][4], bh[2][4];
      const int arow = wm * 64 + (lane & 15);
      const int achunk = kc * 2 + (lane >> 4);
#pragma unroll
      for (int mt = 0; mt < 4; mt++) {
        int rr = arow + mt * 16;
        ldsm_x4(ah[mt], Ab + soff(rr, achunk));
      }
      const int nrow = wn * 32 + ((lane >> 4) << 3) + (lane & 7);
      const int bchunk = kc * 2 + ((lane >> 3) & 1);
#pragma unroll
      for (int bt = 0; bt < 2; bt++) {
        int rr = nrow + bt * 16;
        ldsm_x4(bh[bt], Bb + soff(rr, bchunk));
      }
#pragma unroll
      for (int mt = 0; mt < 4; mt++) {
#pragma unroll
        for (int nt = 0; nt < 4; nt++) {
          mma_f16(acc[mt][nt], ah[mt], &bh[nt >> 1][(nt & 1) * 2]);
        }
      }
    }
    __syncthreads();
  }

  // ---- epilogue: bias + fp16 store ----
  const float* __restrict__ biasp = (p == 0) ? qb : (p == 1) ? kb : vb;
  __half* __restrict__ Out = g_QKV[p] + (size_t)b * C_ * HW_;
  const int mrow_base = m0 + wm * 64 + (lane >> 2);
  const int ncol_base = n0 + wn * 32 + (lane & 3) * 2;

#pragma unroll
  for (int mt = 0; mt < 4; mt++) {
    int mr = mrow_base + mt * 16;
    float bi0 = __ldg(biasp + mr);
    float bi1 = __ldg(biasp + mr + 8);
#pragma unroll
    for (int nt = 0; nt < 4; nt++) {
      int nc = ncol_base + nt * 8;
      *(__half2*)(Out + (size_t)mr * HW_ + nc) =
          __floats2half2_rn(acc[mt][nt][0] + bi0, acc[mt][nt][1] + bi0);
      *(__half2*)(Out + (size_t)(mr + 8) * HW_ + nc) =
          __floats2half2_rn(acc[mt][nt][2] + bi1, acc[mt][nt][3] + bi1);
    }
  }
}

// ---------------------------------------------------------------------------
// Kernel 2: per-channel 3x3-neighbor token attention. Q,K,V fp16.
// 2 channels per thread for doubled memory-level parallelism.
// ---------------------------------------------------------------------------
__global__ void __launch_bounds__(128) attn_kernel(float* __restrict__ out) {
  const int j = threadIdx.x;                    // 0..31
  const int i = blockIdx.x;                     // 0..31
  const int c0 = blockIdx.y * 8 + threadIdx.y * 2;  // this thread: c0, c0+1
  const int b = blockIdx.z;

  const size_t base = ((size_t)b * C_ + c0) * HW_;  // +HW_ for second channel
  const __half* __restrict__ Qp = g_QKV[0] + base;
  const __half* __restrict__ Kp = g_QKV[1] + base;
  const __half* __restrict__ Vp = g_QKV[2] + base;

  const int y0 = i * 4;
  const int x0 = j * 4;
  const int tok = y0 * W_ + x0;

  float4 q[2][4];
#pragma unroll
  for (int cc = 0; cc < 2; cc++) {
    const __half* qp = Qp + cc * HW_ + tok;
#pragma unroll
    for (int r = 0; r < 4; r++) q[cc][r] = ld_h4(qp + r * W_);
  }

  float lg[2][9];
  float mx[2] = {-1e30f, -1e30f};
#pragma unroll
  for (int n = 0; n < 9; n++) {
    const int ii = i + n / 3 - 1;
    const int jj = j + n % 3 - 1;
    const bool ok = (unsigned)ii < (unsigned)NH && (unsigned)jj < (unsigned)NW;
    const int ntok = (ii * 4) * W_ + jj * 4;
#pragma unroll
    for (int cc = 0; cc < 2; cc++) {
      float d = -1e30f;
      if (ok) {
        const __half* kp = Kp + cc * HW_ + ntok;
        float4 k0 = ld_h4(kp);
        float4 k1 = ld_h4(kp + W_);
        float4 k2 = ld_h4(kp + 2 * W_);
        float4 k3 = ld_h4(kp + 3 * W_);
        d  = q[cc][0].x * k0.x + q[cc][0].y * k0.y + q[cc][0].z * k0.z + q[cc][0].w * k0.w;
        d += q[cc][1].x * k1.x + q[cc][1].y * k1.y + q[cc][1].z * k1.z + q[cc][1].w * k1.w;
        d += q[cc][2].x * k2.x + q[cc][2].y * k2.y + q[cc][2].z * k2.z + q[cc][2].w * k2.w;
        d += q[cc][3].x * k3.x + q[cc][3].y * k3.y + q[cc][3].z * k3.z + q[cc][3].w * k3.w;
        d *= 0.25f;
      }
      lg[cc][n] = d;
      mx[cc] = fmaxf(mx[cc], d);
    }
  }

  float wn[2][9];
  float inv[2];
#pragma unroll
  for (int cc = 0; cc < 2; cc++) {
    float wsum = 0.f;
#pragma unroll
    for (int n = 0; n < 9; n++) {
      float e = __expf(lg[cc][n] - mx[cc]);
      wn[cc][n] = e;
      wsum += e;
    }
    inv[cc] = 1.f / wsum;
  }

  float4 o[2][4];
#pragma unroll
  for (int cc = 0; cc < 2; cc++)
#pragma unroll
    for (int r = 0; r < 4; r++) o[cc][r] = make_float4(0.f, 0.f, 0.f, 0.f);

#pragma unroll
  for (int n = 0; n < 9; n++) {
    const int ii = i + n / 3 - 1;
    const int jj = j + n % 3 - 1;
    const bool ok = (unsigned)ii < (unsigned)NH && (unsigned)jj < (unsigned)NW;
    const int ntok = (ii * 4) * W_ + jj * 4;
#pragma unroll
    for (int cc = 0; cc < 2; cc++) {
      if (ok) {
        const float a = wn[cc][n] * inv[cc];
        const __half* vp = Vp + cc * HW_ + ntok;
#pragma unroll
        for (int r = 0; r < 4; r++) {
          float4 v = ld_h4(vp + r * W_);
          o[cc][r].x = fmaf(a, v.x, o[cc][r].x);
          o[cc][r].y = fmaf(a, v.y, o[cc][r].y);
          o[cc][r].z = fmaf(a, v.z, o[cc][r].z);
          o[cc][r].w = fmaf(a, v.w, o[cc][r].w);
        }
      }
    }
  }

#pragma unroll
  for (int cc = 0; cc < 2; cc++) {
    float* op = out + base + cc * HW_ + tok;
#pragma unroll
    for (int r = 0; r < 4; r++) *(float4*)(op + r * W_) = o[cc][r];
  }
}

// ---------------------------------------------------------------------------
extern "C" void kernel_launch(void* const* d_in, const int* in_sizes, int n_in,
                              void* d_out, int out_size) {
  const float* blue  = (const float*)d_in[0];
  const float* white = (const float*)d_in[1];
  const float* qw    = (const float*)d_in[2];
  const float* qb    = (const float*)d_in[3];
  const float* kw    = (const float*)d_in[4];
  const float* kb    = (const float*)d_in[5];
  const float* vw    = (const float*)d_in[6];
  const float* vb    = (const float*)d_in[7];

  const int smem_bytes = 32768;
  cudaFuncSetAttribute(gemm_mma_kernel, cudaFuncAttributeMaxDynamicSharedMemorySize,
                       smem_bytes);

  convert_w_kernel<<<(3 * C_ * C_) / 256, 256>>>(qw, kw, vw);
  convert_x_kernel<<<dim3(HW_ / 32, C_ / 32, 4), dim3(32, 8)>>>(blue, white);
  gemm_mma_kernel<<<dim3(HW_ / 128, C_ / 128, 3 * B_), 256, smem_bytes>>>(qb, kb, vb);
  attn_kernel<<<dim3(NH, C_ / 8, B_), dim3(NW, 4)>>>((float*)d_out);
}

// round 7
// speedup vs baseline: 1.0418x; 1.0418x over previous
#include <cuda_runtime.h>
#include <cuda_fp16.h>
#include <cstdint>

#define B_  2
#define C_  256
#define H_  128
#define W_  128
#define HW_ (H_ * W_)
#define NH  32
#define NW  32

// ---------------------------------------------------------------------------
// Static scratch (no runtime allocation allowed).
// ---------------------------------------------------------------------------
__device__ __align__(256) __half g_Wh[3][C_ * C_];           // fp16(W), [O][K]
__device__ __align__(256) __half g_Xh[4][(size_t)HW_ * C_];  // fp16(X^T), [hw][c]
__device__ __align__(256) __half g_QKV[3][(size_t)B_ * C_ * HW_]; // Q,K,V fp16 [b][c][hw]

// ---------------------------------------------------------------------------
// Helpers
// ---------------------------------------------------------------------------
__device__ __forceinline__ uint32_t smem_u32(const void* p) {
  uint32_t a;
  asm("{ .reg .u64 t; cvta.to.shared.u64 t, %1; cvt.u32.u64 %0, t; }" : "=r"(a) : "l"(p));
  return a;
}

#define CP_ASYNC16(s, g) \
  asm volatile("cp.async.cg.shared.global [%0], [%1], 16;" :: "r"(s), "l"(g))
#define CP_COMMIT() asm volatile("cp.async.commit_group;" ::: "memory")
#define CP_WAIT0()  asm volatile("cp.async.wait_group 0;" ::: "memory")
#define CP_WAIT1()  asm volatile("cp.async.wait_group 1;" ::: "memory")

__device__ __forceinline__ void ldsm_x4(uint32_t* r, uint32_t addr) {
  asm volatile("ldmatrix.sync.aligned.m8n8.x4.shared.b16 {%0,%1,%2,%3}, [%4];"
               : "=r"(r[0]), "=r"(r[1]), "=r"(r[2]), "=r"(r[3]) : "r"(addr));
}

__device__ __forceinline__ void mma_f16(float* c, const uint32_t* a, const uint32_t* b) {
  asm volatile(
      "mma.sync.aligned.m16n8k16.row.col.f32.f16.f16.f32 "
      "{%0,%1,%2,%3}, {%4,%5,%6,%7}, {%8,%9}, {%0,%1,%2,%3};"
      : "+f"(c[0]), "+f"(c[1]), "+f"(c[2]), "+f"(c[3])
      : "r"(a[0]), "r"(a[1]), "r"(a[2]), "r"(a[3]), "r"(b[0]), "r"(b[1]));
}

// smem tile: 128 rows x 32 fp16 (64B rows, 4 x 16B chunks, XOR swizzle)
__device__ __forceinline__ uint32_t soff(int r, int c) {
  return (uint32_t)(r * 64 + ((c ^ ((r >> 1) & 3)) << 4));
}

// ---------------------------------------------------------------------------
// Kernel 0a: weights -> fp16.
// ---------------------------------------------------------------------------
__global__ void __launch_bounds__(256) convert_w_kernel(
    const float* __restrict__ qw, const float* __restrict__ kw,
    const float* __restrict__ vw) {
  int idx = blockIdx.x * 256 + threadIdx.x;
  int p = idx >> 16;
  int r = idx & 0xFFFF;
  const float* w = (p == 0) ? qw : (p == 1) ? kw : vw;
  g_Wh[p][r] = __float2half_rn(w[r]);
}

// ---------------------------------------------------------------------------
// Kernel 0b: transpose X [c][hw] -> [hw][c] into fp16.
// ---------------------------------------------------------------------------
__global__ void __launch_bounds__(256) convert_x_kernel(
    const float* __restrict__ blue, const float* __restrict__ white) {
  __shared__ float t[32][33];
  const int hw0 = blockIdx.x * 32;
  const int c0 = blockIdx.y * 32;
  const int slab = blockIdx.z;
  const float* src = (slab < 2) ? blue + (size_t)slab * C_ * HW_
                                : white + (size_t)(slab - 2) * C_ * HW_;
  const int tx = threadIdx.x, ty = threadIdx.y;
#pragma unroll
  for (int it = 0; it < 4; it++) {
    int c = it * 8 + ty;
    t[c][tx] = src[(size_t)(c0 + c) * HW_ + hw0 + tx];
  }
  __syncthreads();
  const int tid = ty * 32 + tx;
  const int cp = tid & 15;
  const int hy = tid >> 4;
  __half* Xh = g_Xh[slab];
#pragma unroll
  for (int it = 0; it < 2; it++) {
    int hw = it * 16 + hy;
    __half2 vh;
    vh.x = __float2half_rn(t[cp * 2][hw]);
    vh.y = __float2half_rn(t[cp * 2 + 1][hw]);
    *(__half2*)(Xh + (size_t)(hw0 + hw) * C_ + c0 + cp * 2) = vh;
  }
}

// ---------------------------------------------------------------------------
// Kernel 1: single-pass fp16 GEMM via mma.sync (HMMA).
// Out[p][b][m][n] = sum_k W[m][k] * X^T[n][k] + bias[m]   (fp16 out)
// CTA: 128(m) x 128(n), BK=32, 8 warps (2x4), warp 64x32, cp.async pipeline.
// ---------------------------------------------------------------------------
__global__ void __launch_bounds__(256, 2) gemm_mma_kernel(
    const float* __restrict__ qb, const float* __restrict__ kb,
    const float* __restrict__ vb) {
  extern __shared__ char sm[];
  const uint32_t sbase = smem_u32(sm);

  const int tid = threadIdx.x;
  const int lane = tid & 31;
  const int wid = tid >> 5;
  const int wm = wid >> 2;          // 0..1
  const int wn = wid & 3;           // 0..3

  const int z = blockIdx.z;         // 0..5
  const int p = z >> 1;
  const int b = z & 1;
  const int m0 = blockIdx.y * 128;
  const int n0 = blockIdx.x * 128;
  const int slab = (p == 0) ? b : 2 + b;

  const __half* __restrict__ gA = g_Wh[p] + m0 * C_;
  const __half* __restrict__ gB = g_Xh[slab] + (size_t)n0 * C_;

  const int stg_r = tid >> 2;           // rows this thread stages (and +64)
  const int stg_c = tid & 3;

  float acc[4][4][4];
#pragma unroll
  for (int mt = 0; mt < 4; mt++)
#pragma unroll
    for (int nt = 0; nt < 4; nt++)
#pragma unroll
      for (int e = 0; e < 4; e++) acc[mt][nt][e] = 0.f;

#define ISSUE_STAGE(ks, buf)                                                     \
  {                                                                              \
    const int k0 = (ks) * 32;                                                    \
    _Pragma("unroll")                                                            \
    for (int it = 0; it < 2; it++) {                                             \
      int r = stg_r + it * 64;                                                   \
      uint32_t so = sbase + (buf) * 16384 + soff(r, stg_c);                      \
      CP_ASYNC16(so,        gA + r * C_ + k0 + stg_c * 8);                       \
      CP_ASYNC16(so + 8192, gB + (size_t)r * C_ + k0 + stg_c * 8);               \
    }                                                                            \
    CP_COMMIT();                                                                 \
  }

  ISSUE_STAGE(0, 0);

  for (int ks = 0; ks < 8; ks++) {
    const int buf = ks & 1;
    if (ks + 1 < 8) {
      ISSUE_STAGE(ks + 1, buf ^ 1);
      CP_WAIT1();
    } else {
      CP_WAIT0();
    }
    __syncthreads();

    const uint32_t Ab = sbase + buf * 16384;
    const uint32_t Bb = Ab + 8192;

#pragma unroll
    for (int kc = 0; kc < 2; kc++) {
      uint32_t ah[4][4], bh[2][4];
      const int arow = wm * 64 + (lane & 15);
      const int achunk = kc * 2 + (lane >> 4);
#pragma unroll
      for (int mt = 0; mt < 4; mt++) {
        int rr = arow + mt * 16;
        ldsm_x4(ah[mt], Ab + soff(rr, achunk));
      }
      const int nrow = wn * 32 + ((lane >> 4) << 3) + (lane & 7);
      const int bchunk = kc * 2 + ((lane >> 3) & 1);
#pragma unroll
      for (int bt = 0; bt < 2; bt++) {
        int rr = nrow + bt * 16;
        ldsm_x4(bh[bt], Bb + soff(rr, bchunk));
      }
#pragma unroll
      for (int mt = 0; mt < 4; mt++) {
#pragma unroll
        for (int nt = 0; nt < 4; nt++) {
          mma_f16(acc[mt][nt], ah[mt], &bh[nt >> 1][(nt & 1) * 2]);
        }
      }
    }
    __syncthreads();
  }

  // ---- epilogue: bias + fp16 store ----
  const float* __restrict__ biasp = (p == 0) ? qb : (p == 1) ? kb : vb;
  __half* __restrict__ Out = g_QKV[p] + (size_t)b * C_ * HW_;
  const int mrow_base = m0 + wm * 64 + (lane >> 2);
  const int ncol_base = n0 + wn * 32 + (lane & 3) * 2;

#pragma unroll
  for (int mt = 0; mt < 4; mt++) {
    int mr = mrow_base + mt * 16;
    float bi0 = __ldg(biasp + mr);
    float bi1 = __ldg(biasp + mr + 8);
#pragma unroll
    for (int nt = 0; nt < 4; nt++) {
      int nc = ncol_base + nt * 8;
      *(__half2*)(Out + (size_t)mr * HW_ + nc) =
          __floats2half2_rn(acc[mt][nt][0] + bi0, acc[mt][nt][1] + bi0);
      *(__half2*)(Out + (size_t)(mr + 8) * HW_ + nc) =
          __floats2half2_rn(acc[mt][nt][2] + bi1, acc[mt][nt][3] + bi1);
    }
  }
}

// ---------------------------------------------------------------------------
// Kernel 2: per-channel 3x3-neighbor token attention. Q,K,V fp16.
// 1 channel per thread; logit dot-products in half2 (HFMA2); V accum fp32.
// ---------------------------------------------------------------------------
__global__ void __launch_bounds__(256) attn_kernel(float* __restrict__ out) {
  const int j = threadIdx.x;                    // 0..31
  const int i = blockIdx.x;                     // 0..31
  const int c = blockIdx.y * 8 + threadIdx.y;
  const int b = blockIdx.z;

  const size_t base = ((size_t)b * C_ + c) * HW_;
  const __half* __restrict__ Qp = g_QKV[0] + base;
  const __half* __restrict__ Kp = g_QKV[1] + base;
  const __half* __restrict__ Vp = g_QKV[2] + base;

  const int y0 = i * 4;
  const int x0 = j * 4;
  const int tok = y0 * W_ + x0;

  // q token as 8 half2 (4 rows x 2 half2)
  __half2 qh[4][2];
#pragma unroll
  for (int r = 0; r < 4; r++) {
    uint2 u = *(const uint2*)(Qp + tok + r * W_);
    qh[r][0] = *(__half2*)&u.x;
    qh[r][1] = *(__half2*)&u.y;
  }

  float lg[9];
  float mx = -1e30f;
#pragma unroll
  for (int n = 0; n < 9; n++) {
    const int ii = i + n / 3 - 1;
    const int jj = j + n % 3 - 1;
    float d = -1e30f;
    if ((unsigned)ii < (unsigned)NH && (unsigned)jj < (unsigned)NW) {
      const __half* kp = Kp + (ii * 4) * W_ + jj * 4;
      __half2 acc = __float2half2_rn(0.f);
#pragma unroll
      for (int r = 0; r < 4; r++) {
        uint2 u = *(const uint2*)(kp + r * W_);
        acc = __hfma2(qh[r][0], *(__half2*)&u.x, acc);
        acc = __hfma2(qh[r][1], *(__half2*)&u.y, acc);
      }
      d = (__low2float(acc) + __high2float(acc)) * 0.25f;
    }
    lg[n] = d;
    mx = fmaxf(mx, d);
  }

  float wn[9];
  float wsum = 0.f;
#pragma unroll
  for (int n = 0; n < 9; n++) {
    float e = __expf(lg[n] - mx);
    wn[n] = e;
    wsum += e;
  }
  const float inv = 1.f / wsum;

  float4 o0 = {0, 0, 0, 0}, o1 = {0, 0, 0, 0}, o2 = {0, 0, 0, 0}, o3 = {0, 0, 0, 0};
#pragma unroll
  for (int n = 0; n < 9; n++) {
    const int ii = i + n / 3 - 1;
    const int jj = j + n % 3 - 1;
    if ((unsigned)ii < (unsigned)NH && (unsigned)jj < (unsigned)NW) {
      const float a = wn[n] * inv;
      const __half* vp = Vp + (ii * 4) * W_ + jj * 4;
#pragma unroll
      for (int r = 0; r < 4; r++) {
        uint2 u = *(const uint2*)(vp + r * W_);
        float2 f0 = __half22float2(*(__half2*)&u.x);
        float2 f1 = __half22float2(*(__half2*)&u.y);
        float4* o = (r == 0) ? &o0 : (r == 1) ? &o1 : (r == 2) ? &o2 : &o3;
        o->x = fmaf(a, f0.x, o->x);
        o->y = fmaf(a, f0.y, o->y);
        o->z = fmaf(a, f1.x, o->z);
        o->w = fmaf(a, f1.y, o->w);
      }
    }
  }

  float* op = out + base + tok;
  *(float4*)(op)          = o0;
  *(float4*)(op + W_)     = o1;
  *(float4*)(op + 2 * W_) = o2;
  *(float4*)(op + 3 * W_) = o3;
}

// ---------------------------------------------------------------------------
extern "C" void kernel_launch(void* const* d_in, const int* in_sizes, int n_in,
                              void* d_out, int out_size) {
  const float* blue  = (const float*)d_in[0];
  const float* white = (const float*)d_in[1];
  const float* qw    = (const float*)d_in[2];
  const float* qb    = (const float*)d_in[3];
  const float* kw    = (const float*)d_in[4];
  const float* kb    = (const float*)d_in[5];
  const float* vw    = (const float*)d_in[6];
  const float* vb    = (const float*)d_in[7];

  const int smem_bytes = 32768;
  cudaFuncSetAttribute(gemm_mma_kernel, cudaFuncAttributeMaxDynamicSharedMemorySize,
                       smem_bytes);

  convert_w_kernel<<<(3 * C_ * C_) / 256, 256>>>(qw, kw, vw);
  convert_x_kernel<<<dim3(HW_ / 32, C_ / 32, 4), dim3(32, 8)>>>(blue, white);
  gemm_mma_kernel<<<dim3(HW_ / 128, C_ / 128, 3 * B_), 256, smem_bytes>>>(qb, kb, vb);
  attn_kernel<<<dim3(NH, C_ / 8, B_), dim3(32, 8)>>>((float*)d_out);
}

// round 8
// speedup vs baseline: 1.1672x; 1.1204x over previous
#include <cuda_runtime.h>
#include <cuda_fp16.h>
#include <cstdint>

#define B_  2
#define C_  256
#define H_  128
#define W_  128
#define HW_ (H_ * W_)
#define NH  32
#define NW  32

// ---------------------------------------------------------------------------
// Static scratch (no runtime allocation allowed).
// ---------------------------------------------------------------------------
__device__ __align__(256) __half g_Wh[3][C_ * C_];                // fp16(W), [O][K]
__device__ __align__(256) __half g_QKV[3][(size_t)B_ * C_ * HW_]; // Q,K,V fp16 [b][c][hw]

// ---------------------------------------------------------------------------
// Helpers
// ---------------------------------------------------------------------------
__device__ __forceinline__ uint32_t smem_u32(const void* p) {
  uint32_t a;
  asm("{ .reg .u64 t; cvta.to.shared.u64 t, %1; cvt.u32.u64 %0, t; }" : "=r"(a) : "l"(p));
  return a;
}

#define CP_ASYNC16(s, g) \
  asm volatile("cp.async.cg.shared.global [%0], [%1], 16;" :: "r"(s), "l"(g))
#define CP_COMMIT() asm volatile("cp.async.commit_group;" ::: "memory")
#define CP_WAIT0()  asm volatile("cp.async.wait_group 0;" ::: "memory")
#define CP_WAIT1()  asm volatile("cp.async.wait_group 1;" ::: "memory")

__device__ __forceinline__ void ldsm_x4(uint32_t* r, uint32_t addr) {
  asm volatile("ldmatrix.sync.aligned.m8n8.x4.shared.b16 {%0,%1,%2,%3}, [%4];"
               : "=r"(r[0]), "=r"(r[1]), "=r"(r[2]), "=r"(r[3]) : "r"(addr));
}
__device__ __forceinline__ void ldsm_x4_t(uint32_t* r, uint32_t addr) {
  asm volatile("ldmatrix.sync.aligned.m8n8.x4.trans.shared.b16 {%0,%1,%2,%3}, [%4];"
               : "=r"(r[0]), "=r"(r[1]), "=r"(r[2]), "=r"(r[3]) : "r"(addr));
}

__device__ __forceinline__ void mma_f16(float* c, const uint32_t* a, const uint32_t* b) {
  asm volatile(
      "mma.sync.aligned.m16n8k16.row.col.f32.f16.f16.f32 "
      "{%0,%1,%2,%3}, {%4,%5,%6,%7}, {%8,%9}, {%0,%1,%2,%3};"
      : "+f"(c[0]), "+f"(c[1]), "+f"(c[2]), "+f"(c[3])
      : "r"(a[0]), "r"(a[1]), "r"(a[2]), "r"(a[3]), "r"(b[0]), "r"(b[1]));
}

// A smem tile: 128 rows x 32 fp16 (64B rows, 4 x 16B chunks, XOR swizzle)
__device__ __forceinline__ uint32_t soff(int r, int c) {
  return (uint32_t)(r * 64 + ((c ^ ((r >> 1) & 3)) << 4));
}
// B smem tile: 32 k-rows x 128 n fp16 (256B rows, 16 x 16B chunks, XOR swizzle)
__device__ __forceinline__ uint32_t boff(int r, int c) {
  return (uint32_t)(r * 256 + ((c ^ (r & 7)) << 4));
}

// ---------------------------------------------------------------------------
// Kernel 0: weights -> fp16.
// ---------------------------------------------------------------------------
__global__ void __launch_bounds__(256) convert_w_kernel(
    const float* __restrict__ qw, const float* __restrict__ kw,
    const float* __restrict__ vw) {
  int idx = blockIdx.x * 256 + threadIdx.x;
  int p = idx >> 16;
  int r = idx & 0xFFFF;
  const float* w = (p == 0) ? qw : (p == 1) ? kw : vw;
  g_Wh[p][r] = __float2half_rn(w[r]);
}

// ---------------------------------------------------------------------------
// Kernel 1: single-pass fp16 GEMM via mma.sync (HMMA), B staged directly
// from fp32 X ([c][hw] layout) with in-kernel fp16 conversion + ldmatrix.trans.
// Out[p][b][m][n] = sum_k W[m][k] * X[k][n] + bias[m]   (fp16 out)
// CTA: 128(m) x 128(n), BK=32, 8 warps (2x4), warp 64x32.
// ---------------------------------------------------------------------------
__global__ void __launch_bounds__(256, 2) gemm_mma_kernel(
    const float* __restrict__ blue, const float* __restrict__ white,
    const float* __restrict__ qb, const float* __restrict__ kb,
    const float* __restrict__ vb) {
  extern __shared__ char sm[];
  const uint32_t sbase = smem_u32(sm);

  const int tid = threadIdx.x;
  const int lane = tid & 31;
  const int wid = tid >> 5;
  const int wm = wid >> 2;          // 0..1
  const int wn = wid & 3;           // 0..3

  const int z = blockIdx.z;         // 0..5
  const int p = z >> 1;
  const int b = z & 1;
  const int m0 = blockIdx.y * 128;
  const int n0 = blockIdx.x * 128;

  const __half* __restrict__ gA = g_Wh[p] + m0 * C_;
  const float* __restrict__ Xsrc =
      ((p == 0) ? blue : white) + (size_t)b * C_ * HW_ + n0;

  // A staging (cp.async): rows tid>>2 (+64), chunk tid&3
  const int stg_ar = tid >> 2;
  const int stg_ac = tid & 3;
  // B staging (LDG+cvt+STS): rows tid>>4 (+16), chunk tid&15 (8 floats each)
  const int stg_br = tid >> 4;
  const int stg_bc = tid & 15;

  float acc[4][4][4];
#pragma unroll
  for (int mt = 0; mt < 4; mt++)
#pragma unroll
    for (int nt = 0; nt < 4; nt++)
#pragma unroll
      for (int e = 0; e < 4; e++) acc[mt][nt][e] = 0.f;

  float4 bf[2][2];   // prefetch regs for B (2 rows x 8 floats)

#define ISSUE_A(ks, buf)                                                        \
  {                                                                             \
    const int k0 = (ks) * 32;                                                   \
    _Pragma("unroll")                                                           \
    for (int it = 0; it < 2; it++) {                                            \
      int r = stg_ar + it * 64;                                                 \
      CP_ASYNC16(sbase + (buf) * 16384 + soff(r, stg_ac),                       \
                 gA + r * C_ + k0 + stg_ac * 8);                                \
    }                                                                           \
    CP_COMMIT();                                                                \
  }

#define LDG_B(ks)                                                               \
  {                                                                             \
    const float* bp = Xsrc + (size_t)((ks) * 32) * HW_;                         \
    _Pragma("unroll")                                                           \
    for (int it = 0; it < 2; it++) {                                            \
      const float* q = bp + (size_t)(stg_br + it * 16) * HW_ + stg_bc * 8;      \
      bf[it][0] = *(const float4*)q;                                            \
      bf[it][1] = *(const float4*)(q + 4);                                      \
    }                                                                           \
  }

#define STS_B(buf)                                                              \
  {                                                                             \
    _Pragma("unroll")                                                           \
    for (int it = 0; it < 2; it++) {                                            \
      int r = stg_br + it * 16;                                                 \
      __half2 h[4];                                                             \
      h[0] = __floats2half2_rn(bf[it][0].x, bf[it][0].y);                       \
      h[1] = __floats2half2_rn(bf[it][0].z, bf[it][0].w);                       \
      h[2] = __floats2half2_rn(bf[it][1].x, bf[it][1].y);                       \
      h[3] = __floats2half2_rn(bf[it][1].z, bf[it][1].w);                       \
      *(uint4*)(sm + (buf) * 16384 + 8192 + boff(r, stg_bc)) = *(uint4*)h;      \
    }                                                                           \
  }

  ISSUE_A(0, 0);
  LDG_B(0);

  for (int ks = 0; ks < 8; ks++) {
    const int buf = ks & 1;
    STS_B(buf);
    if (ks + 1 < 8) {
      LDG_B(ks + 1);
      ISSUE_A(ks + 1, buf ^ 1);
      CP_WAIT1();
    } else {
      CP_WAIT0();
    }
    __syncthreads();

    const uint32_t Ab = sbase + buf * 16384;
    const uint32_t Bb = Ab + 8192;

#pragma unroll
    for (int kc = 0; kc < 2; kc++) {
      uint32_t ah[4][4], bh[2][4];
      const int arow = wm * 64 + (lane & 15);
      const int achunk = kc * 2 + (lane >> 4);
#pragma unroll
      for (int mt = 0; mt < 4; mt++) {
        int rr = arow + mt * 16;
        ldsm_x4(ah[mt], Ab + soff(rr, achunk));
      }
      // B via trans ldmatrix from [k][n] tile:
      // group0: k0-7/n0-7, group1: k8-15/n0-7, group2: k0-7/n8-15, group3: k8-15/n8-15
      const int brow = kc * 16 + ((lane >> 3) & 1) * 8 + (lane & 7);
#pragma unroll
      for (int bt = 0; bt < 2; bt++) {
        int cb = wn * 4 + bt * 2 + (lane >> 4);
        ldsm_x4_t(bh[bt], Bb + boff(brow, cb));
      }
#pragma unroll
      for (int mt = 0; mt < 4; mt++) {
#pragma unroll
        for (int nt = 0; nt < 4; nt++) {
          mma_f16(acc[mt][nt], ah[mt], &bh[nt >> 1][(nt & 1) * 2]);
        }
      }
    }
    __syncthreads();
  }

  // ---- epilogue: bias + fp16 store ----
  const float* __restrict__ biasp = (p == 0) ? qb : (p == 1) ? kb : vb;
  __half* __restrict__ Out = g_QKV[p] + (size_t)b * C_ * HW_;
  const int mrow_base = m0 + wm * 64 + (lane >> 2);
  const int ncol_base = n0 + wn * 32 + (lane & 3) * 2;

#pragma unroll
  for (int mt = 0; mt < 4; mt++) {
    int mr = mrow_base + mt * 16;
    float bi0 = __ldg(biasp + mr);
    float bi1 = __ldg(biasp + mr + 8);
#pragma unroll
    for (int nt = 0; nt < 4; nt++) {
      int nc = ncol_base + nt * 8;
      *(__half2*)(Out + (size_t)mr * HW_ + nc) =
          __floats2half2_rn(acc[mt][nt][0] + bi0, acc[mt][nt][1] + bi0);
      *(__half2*)(Out + (size_t)(mr + 8) * HW_ + nc) =
          __floats2half2_rn(acc[mt][nt][2] + bi1, acc[mt][nt][3] + bi1);
    }
  }
}

// ---------------------------------------------------------------------------
// Kernel 2: per-channel 3x3-neighbor token attention. Q,K,V fp16.
// 1 channel per thread; logit dot-products in half2 (HFMA2); V accum fp32.
// ---------------------------------------------------------------------------
__global__ void __launch_bounds__(256) attn_kernel(float* __restrict__ out) {
  const int j = threadIdx.x;                    // 0..31
  const int i = blockIdx.x;                     // 0..31
  const int c = blockIdx.y * 8 + threadIdx.y;
  const int b = blockIdx.z;

  const size_t base = ((size_t)b * C_ + c) * HW_;
  const __half* __restrict__ Qp = g_QKV[0] + base;
  const __half* __restrict__ Kp = g_QKV[1] + base;
  const __half* __restrict__ Vp = g_QKV[2] + base;

  const int y0 = i * 4;
  const int x0 = j * 4;
  const int tok = y0 * W_ + x0;

  __half2 qh[4][2];
#pragma unroll
  for (int r = 0; r < 4; r++) {
    uint2 u = *(const uint2*)(Qp + tok + r * W_);
    qh[r][0] = *(__half2*)&u.x;
    qh[r][1] = *(__half2*)&u.y;
  }

  float lg[9];
  float mx = -1e30f;
#pragma unroll
  for (int n = 0; n < 9; n++) {
    const int ii = i + n / 3 - 1;
    const int jj = j + n % 3 - 1;
    float d = -1e30f;
    if ((unsigned)ii < (unsigned)NH && (unsigned)jj < (unsigned)NW) {
      const __half* kp = Kp + (ii * 4) * W_ + jj * 4;
      __half2 acc = __float2half2_rn(0.f);
#pragma unroll
      for (int r = 0; r < 4; r++) {
        uint2 u = *(const uint2*)(kp + r * W_);
        acc = __hfma2(qh[r][0], *(__half2*)&u.x, acc);
        acc = __hfma2(qh[r][1], *(__half2*)&u.y, acc);
      }
      d = (__low2float(acc) + __high2float(acc)) * 0.25f;
    }
    lg[n] = d;
    mx = fmaxf(mx, d);
  }

  float wn[9];
  float wsum = 0.f;
#pragma unroll
  for (int n = 0; n < 9; n++) {
    float e = __expf(lg[n] - mx);
    wn[n] = e;
    wsum += e;
  }
  const float inv = 1.f / wsum;

  float4 o0 = {0, 0, 0, 0}, o1 = {0, 0, 0, 0}, o2 = {0, 0, 0, 0}, o3 = {0, 0, 0, 0};
#pragma unroll
  for (int n = 0; n < 9; n++) {
    const int ii = i + n / 3 - 1;
    const int jj = j + n % 3 - 1;
    if ((unsigned)ii < (unsigned)NH && (unsigned)jj < (unsigned)NW) {
      const float a = wn[n] * inv;
      const __half* vp = Vp + (ii * 4) * W_ + jj * 4;
#pragma unroll
      for (int r = 0; r < 4; r++) {
        uint2 u = *(const uint2*)(vp + r * W_);
        float2 f0 = __half22float2(*(__half2*)&u.x);
        float2 f1 = __half22float2(*(__half2*)&u.y);
        float4* o = (r == 0) ? &o0 : (r == 1) ? &o1 : (r == 2) ? &o2 : &o3;
        o->x = fmaf(a, f0.x, o->x);
        o->y = fmaf(a, f0.y, o->y);
        o->z = fmaf(a, f1.x, o->z);
        o->w = fmaf(a, f1.y, o->w);
      }
    }
  }

  float* op = out + base + tok;
  *(float4*)(op)          = o0;
  *(float4*)(op + W_)     = o1;
  *(float4*)(op + 2 * W_) = o2;
  *(float4*)(op + 3 * W_) = o3;
}

// ---------------------------------------------------------------------------
extern "C" void kernel_launch(void* const* d_in, const int* in_sizes, int n_in,
                              void* d_out, int out_size) {
  const float* blue  = (const float*)d_in[0];
  const float* white = (const float*)d_in[1];
  const float* qw    = (const float*)d_in[2];
  const float* qb    = (const float*)d_in[3];
  const float* kw    = (const float*)d_in[4];
  const float* kb    = (const float*)d_in[5];
  const float* vw    = (const float*)d_in[6];
  const float* vb    = (const float*)d_in[7];

  const int smem_bytes = 32768;
  cudaFuncSetAttribute(gemm_mma_kernel, cudaFuncAttributeMaxDynamicSharedMemorySize,
                       smem_bytes);

  convert_w_kernel<<<(3 * C_ * C_) / 256, 256>>>(qw, kw, vw);
  gemm_mma_kernel<<<dim3(HW_ / 128, C_ / 128, 3 * B_), 256, smem_bytes>>>(
      blue, white, qb, kb, vb);
  attn_kernel<<<dim3(NH, C_ / 8, B_), dim3(32, 8)>>>((float*)d_out);
}